// round 9
// baseline (speedup 1.0000x reference)
#include <cuda_runtime.h>
#include <cuda_bf16.h>
#include <math.h>

// Problem constants
#define BB    512
#define SS    256
#define IDIM  32
#define HH    256
#define OO    24

// Geometry
#define CL     8                  // CTAs per cluster
#define ROWS   32                 // batch rows per cluster
#define NCLU   (BB/ROWS)          // 16 clusters
#define GRID_R (NCLU*CL)          // 128 CTAs
#define NTHR   512                // 16 warps: 0-3 GEMM, 4-7 x-stage, 8-15 pointwise
#define KTOT   288                // 256 h + 32 x
#define NCH    18                 // 18 k16 chunks

#define ASTRIDE 592               // bytes per k-row (576 + 16 pad: conflict-free ldmatrix)
#define A_BYTES (128*ASTRIDE)     // 75776 per precision
#define B_BYTES (32*ASTRIDE)      // 18944 per precision

// SMEM offsets (bytes)
#define A_HI   0
#define A_LO   75776
#define B_HI   151552
#define B_LO   170496
#define ACCO   189440             // float [32 n][132] (LDS.128-aligned rows)
#define SMEM_BYTES 206336

// Device scratch
__device__ __align__(16) unsigned char g_Ahi[CL*A_BYTES];
__device__ __align__(16) unsigned char g_Alo[CL*A_BYTES];
__device__ float g_bc[CL*128];    // composed bias [rank][m = c*4+q]
__device__ float g_hfinal[BB*HH];

typedef unsigned long long u64;

// ---------------- helpers ----------------
__device__ __forceinline__ unsigned s2u(const void *p) {
    unsigned r;
    asm("{.reg .u64 t; cvta.to.shared.u64 t,%1; cvt.u32.u64 %0,t;}" : "=r"(r) : "l"(p));
    return r;
}
__device__ __forceinline__ unsigned mapa_sh(unsigned a, unsigned r) {
    unsigned o; asm("mapa.shared::cluster.u32 %0,%1,%2;" : "=r"(o) : "r"(a), "r"(r)); return o;
}
__device__ __forceinline__ void stc64(unsigned a, u64 v) {
    asm volatile("st.shared::cluster.b64 [%0],%1;" :: "r"(a), "l"(v) : "memory");
}
__device__ __forceinline__ void carr() { asm volatile("barrier.cluster.arrive.aligned;" ::: "memory"); }
__device__ __forceinline__ void cwait(){ asm volatile("barrier.cluster.wait.aligned;"   ::: "memory"); }
__device__ __forceinline__ void csync(){ carr(); cwait(); }

__device__ __forceinline__ void ldm4(unsigned* r, unsigned a) {
    asm volatile("ldmatrix.sync.aligned.m8n8.x4.shared.b16 {%0,%1,%2,%3},[%4];"
        : "=r"(r[0]), "=r"(r[1]), "=r"(r[2]), "=r"(r[3]) : "r"(a));
}
__device__ __forceinline__ void mma16816(float* d, const unsigned* a, unsigned b0, unsigned b1) {
    asm volatile("mma.sync.aligned.m16n8k16.row.col.f32.bf16.bf16.f32 "
        "{%0,%1,%2,%3},{%4,%5,%6,%7},{%8,%9},{%0,%1,%2,%3};"
        : "+f"(d[0]), "+f"(d[1]), "+f"(d[2]), "+f"(d[3])
        : "r"(a[0]), "r"(a[1]), "r"(a[2]), "r"(a[3]), "r"(b0), "r"(b1));
}

__device__ __forceinline__ float fast_tanh(float x) {
    return 1.f - __fdividef(2.f, __expf(2.f*x) + 1.f);
}
__device__ __forceinline__ void split4(const float* v, u64 &vh, u64 &vl) {
    u64 H = 0, L = 0;
    #pragma unroll
    for (int j = 0; j < 4; ++j) {
        __nv_bfloat16 bh = __float2bfloat16(v[j]);
        float fh = __bfloat162float(bh);
        __nv_bfloat16 bl = __float2bfloat16(v[j] - fh);
        H |= (u64)__bfloat16_as_ushort(bh) << (16*j);
        L |= (u64)__bfloat16_as_ushort(bl) << (16*j);
    }
    vh = H; vl = L;
}

// ---------------------------------------------------------------------------
// prep: bf16 hi/lo weight images [rank][m][k], m = c*4+q <-> gate g = q*256+rank*32+c
// ---------------------------------------------------------------------------
__global__ void prep_kernel(const float* __restrict__ W, const float* __restrict__ R,
                            const float* __restrict__ b, const float* __restrict__ b_in,
                            const float* __restrict__ W_in)
{
    int idx = blockIdx.x * blockDim.x + threadIdx.x;
    if (idx < CL*128*296) {
        int kk   = idx % 296;
        int m    = (idx / 296) % 128;
        int rank = idx / (296*128);
        int c = m >> 2, q = m & 3;
        int g = q*256 + rank*32 + c;
        float w = 0.f;
        if (kk < 256) {
            w = W[(size_t)g*512 + 256 + kk] + R[(size_t)g*256 + kk];
        } else if (kk < 288) {
            int i = kk - 256;
            float s = 0.f;
            for (int h = 0; h < HH; ++h) s += W[(size_t)g*512 + h] * W_in[(size_t)h*IDIM + i];
            w = s;
        }
        __nv_bfloat16 hi = __float2bfloat16(w);
        __nv_bfloat16 lo = __float2bfloat16(w - __bfloat162float(hi));
        size_t off = (size_t)rank*A_BYTES + (size_t)m*ASTRIDE + kk*2;
        *(__nv_bfloat16*)(g_Ahi + off) = hi;
        *(__nv_bfloat16*)(g_Alo + off) = lo;
    }
    if (idx < CL*128) {
        int m = idx & 127, rank = idx >> 7;
        int c = m >> 2, q = m & 3;
        int g = q*256 + rank*32 + c;
        float s = b[g];
        for (int h = 0; h < HH; ++h) s += W[(size_t)g*512 + h] * b_in[h];
        g_bc[idx] = s;
    }
}

__global__ void dummy_kernel() {}

// ---------------------------------------------------------------------------
// Recurrence: HMMA 3-term hi/lo per step; cluster of 8 shares h.
// warps 0-3 GEMM (m32 each) -> acc[n][m]; warps 4-7 stage x; warps 8-15
// pointwise (thread = (c-quad, n)) fused with DSMEM broadcast.
// ---------------------------------------------------------------------------
__global__ void __cluster_dims__(CL, 1, 1) __launch_bounds__(NTHR, 1)
recur_kernel(const float* __restrict__ x)
{
    extern __shared__ unsigned char smem[];
    const unsigned base = s2u(smem);
    float* accS = (float*)(smem + ACCO);

    unsigned rank; asm("mov.u32 %0, %%cluster_ctarank;" : "=r"(rank));
    const int cid  = blockIdx.x >> 3;
    const int b0   = cid * ROWS;
    const int tid  = threadIdx.x;
    const int lane = tid & 31;
    const int warp = tid >> 5;

    // ---- load resident A tiles, zero B ----
    {
        const float4* sa = (const float4*)(g_Ahi + (size_t)rank*A_BYTES);
        const float4* sb = (const float4*)(g_Alo + (size_t)rank*A_BYTES);
        float4* da = (float4*)(smem + A_HI);
        float4* db = (float4*)(smem + A_LO);
        for (int i = tid; i < A_BYTES/16; i += NTHR) { da[i] = sa[i]; db[i] = sb[i]; }
        float4 z = make_float4(0.f,0.f,0.f,0.f);
        float4* bz = (float4*)(smem + B_HI);
        for (int i = tid; i < (2*B_BYTES)/16; i += NTHR) bz[i] = z;
    }
    __syncthreads();

    // ---- x stager plumbing (warps 4-7): 128 threads, (n, 8 features) ----
    const int sidx = tid - 128;                 // valid for warps 4-7
    const int n_s  = (sidx >> 2) & 31;
    const int q_s  = sidx & 3;
    const float* xrb = x + (size_t)(b0 + n_s)*SS*IDIM + q_s*8;
    unsigned char* xpH = smem + B_HI + n_s*ASTRIDE + 512 + q_s*16;
    unsigned char* xpL = smem + B_LO + n_s*ASTRIDE + 512 + q_s*16;

    if (warp >= 4 && warp < 8) {   // stage x(0)
        float4 a0 = *(const float4*)(xrb);
        float4 a1 = *(const float4*)(xrb + 4);
        float v0[4] = {a0.x,a0.y,a0.z,a0.w}, v1[4] = {a1.x,a1.y,a1.z,a1.w};
        u64 h0,l0,h1,l1; split4(v0,h0,l0); split4(v1,h1,l1);
        ((ulonglong2*)xpH)[0] = make_ulonglong2(h0,h1);
        ((ulonglong2*)xpL)[0] = make_ulonglong2(l0,l1);
    }
    __syncthreads();
    csync();                       // B(0) ready cluster-wide

    // ---- GEMM lane addresses (warps 0-3) ----
    const unsigned aH  = base + A_HI + (unsigned)(warp*32 + (lane & 15))*ASTRIDE + (lane >> 4)*16;
    const unsigned aL  = aH + (A_LO - A_HI);
    const unsigned bHa = base + B_HI + (unsigned)lane*ASTRIDE;
    const unsigned bLa = bHa + (B_LO - B_HI);

    // ---- pointwise plumbing (warps 8-15): thread = (cq = pidx>>5, n = pidx&31) ----
    const int pidx = tid - 256;
    const int n_p  = pidx & 31;
    const int cq   = (pidx >> 5) & 7;
    float bias[4][4];
    float cst[4], nst[4], mst[4];
    unsigned raH[CL], raL[CL];
    float* ghf = g_hfinal + (size_t)(b0 + n_p)*HH + rank*32 + cq*4;
    const float* accRd = accS + n_p*132 + cq*16;
    if (warp >= 8) {
        #pragma unroll
        for (int j = 0; j < 4; ++j) {
            float4 b4 = ((const float4*)g_bc)[rank*32 + cq*4 + j];
            bias[j][0]=b4.x; bias[j][1]=b4.y; bias[j][2]=b4.z; bias[j][3]=b4.w;
        }
        #pragma unroll
        for (int j = 0; j < 4; ++j) { cst[j]=0.f; nst[j]=0.f; mst[j]=0.f; }
        unsigned off = (unsigned)n_p*ASTRIDE + (rank*32 + cq*4)*2;
        #pragma unroll
        for (unsigned r = 0; r < CL; ++r) {
            raH[r] = mapa_sh(base + B_HI + off, r);
            raL[r] = mapa_sh(base + B_LO + off, r);
        }
    }

    for (int t = 0; t < SS; ++t) {
        // stagers: issue x(t+1) LDG early
        float4 xv0, xv1;
        if (warp >= 4 && warp < 8 && t + 1 < SS) {
            xv0 = *(const float4*)(xrb + (size_t)(t+1)*IDIM);
            xv1 = *(const float4*)(xrb + (size_t)(t+1)*IDIM + 4);
        }

        // ---- GEMM (warps 0-3): 32m x 32n x 288k, 3-term hi/lo ----
        if (warp < 4) {
            float d[2][4][4];
            #pragma unroll
            for (int mi = 0; mi < 2; ++mi)
                #pragma unroll
                for (int nj = 0; nj < 4; ++nj)
                    #pragma unroll
                    for (int e = 0; e < 4; ++e) d[mi][nj][e] = 0.f;

            #pragma unroll 6
            for (int ch = 0; ch < NCH; ++ch) {
                unsigned ka = ch*32;
                unsigned AH0[4], AH1[4], AL0[4], AL1[4], BHp[4], BHq[4], BLp[4], BLq[4];
                ldm4(AH0, aH + ka); ldm4(AH1, aH + 16*ASTRIDE + ka);
                ldm4(AL0, aL + ka); ldm4(AL1, aL + 16*ASTRIDE + ka);
                ldm4(BHp, bHa + ka); ldm4(BHq, bHa + ka + 16);
                ldm4(BLp, bLa + ka); ldm4(BLq, bLa + ka + 16);
                #pragma unroll
                for (int nj = 0; nj < 4; ++nj) {
                    mma16816(d[0][nj], AH0, BHp[nj], BHq[nj]);
                    mma16816(d[0][nj], AL0, BHp[nj], BHq[nj]);
                    mma16816(d[0][nj], AH0, BLp[nj], BLq[nj]);
                    mma16816(d[1][nj], AH1, BHp[nj], BHq[nj]);
                    mma16816(d[1][nj], AL1, BHp[nj], BHq[nj]);
                    mma16816(d[1][nj], AH1, BLp[nj], BLq[nj]);
                }
            }
            // fragment store into acc[n][m] (conflict-free STS.32)
            #pragma unroll
            for (int mi = 0; mi < 2; ++mi) {
                int m = warp*32 + mi*16 + (lane >> 2);
                #pragma unroll
                for (int nj = 0; nj < 4; ++nj) {
                    int n0 = nj*8 + (lane & 3)*2;
                    accS[n0*132 + m]       = d[mi][nj][0];
                    accS[(n0+1)*132 + m]   = d[mi][nj][1];
                    accS[n0*132 + m + 8]   = d[mi][nj][2];
                    accS[(n0+1)*132 + m + 8] = d[mi][nj][3];
                }
            }
        }

        __syncthreads();           // acc ready; all local B(t) reads done
        carr();                    // sync1 arrive: my CTA done reading B(t)

        // stagers: write x(t+1) into local B (own region; own GEMM done reading)
        if (warp >= 4 && warp < 8 && t + 1 < SS) {
            float v0[4] = {xv0.x,xv0.y,xv0.z,xv0.w}, v1[4] = {xv1.x,xv1.y,xv1.z,xv1.w};
            u64 h0,l0,h1,l1; split4(v0,h0,l0); split4(v1,h1,l1);
            ((ulonglong2*)xpH)[0] = make_ulonglong2(h0,h1);
            ((ulonglong2*)xpL)[0] = make_ulonglong2(l0,l1);
        }

        // pointwise compute (hides under sync1 skew)
        float hv[4];
        if (warp >= 8) {
            #pragma unroll
            for (int j = 0; j < 4; ++j) {
                float4 g4 = *(const float4*)(accRd + j*4);
                float gi = g4.x + bias[j][0];
                float gf = g4.y + bias[j][1];
                float gz = g4.z + bias[j][2];
                float go = g4.w + bias[j][3];
                float lf  = -__logf(1.f + __expf(-gf));
                float mn  = fmaxf(lf + mst[j], gi);
                float ipr = __expf(gi - mn);
                float fp  = __expf(lf + mst[j] - mn);
                float cn  = fp*cst[j] + ipr*fast_tanh(gz);
                float nn  = fp*nst[j] + ipr;
                float so  = __fdividef(1.f, 1.f + __expf(-go));
                hv[j] = so * fast_tanh(__fdividef(cn, nn));
                cst[j]=cn; nst[j]=nn; mst[j]=mn;
            }
        }

        cwait();                   // sync1 done: all CTAs finished reading B(t)

        if (warp >= 8) {
            if (t + 1 < SS) {
                u64 vH, vL; split4(hv, vH, vL);
                #pragma unroll
                for (unsigned r = 0; r < CL; ++r) { stc64(raH[r], vH); stc64(raL[r], vL); }
            } else {
                *(float4*)ghf = make_float4(hv[0], hv[1], hv[2], hv[3]);
            }
        }

        carr(); cwait();           // sync2: B(t+1) fully written cluster-wide
    }
}

// ---------------------------------------------------------------------------
// Epilogue: out = h @ W_out^T + b_out, then layernorm over O=24
// ---------------------------------------------------------------------------
__global__ void __launch_bounds__(64) epi_kernel(const float* __restrict__ Wo,
                                                 const float* __restrict__ bo,
                                                 float* __restrict__ out)
{
    __shared__ float hrow[HH];
    __shared__ float ov[OO];
    __shared__ float s_mu, s_rs;
    int b = blockIdx.x, tid = threadIdx.x;

    const float4* hs = (const float4*)(g_hfinal + (size_t)b*HH);
    for (int i = tid; i < HH/4; i += 64) ((float4*)hrow)[i] = hs[i];
    __syncthreads();

    if (tid < OO) {
        float s = bo[tid];
        const float* w = Wo + (size_t)tid*HH;
        #pragma unroll 8
        for (int k = 0; k < HH; ++k) s += hrow[k]*w[k];
        ov[tid] = s;
    }
    __syncthreads();
    if (tid == 0) {
        float mu = 0.f;
        for (int o = 0; o < OO; ++o) mu += ov[o];
        mu *= (1.f/OO);
        float va = 0.f;
        for (int o = 0; o < OO; ++o) { float d = ov[o]-mu; va += d*d; }
        va *= (1.f/OO);
        s_mu = mu; s_rs = rsqrtf(va + 1e-5f);
    }
    __syncthreads();
    if (tid < OO) out[(size_t)b*OO + tid] = (ov[tid]-s_mu)*s_rs;
}

// ---------------------------------------------------------------------------
extern "C" void kernel_launch(void* const* d_in, const int* in_sizes, int n_in,
                              void* d_out, int out_size)
{
    (void)in_sizes; (void)n_in; (void)out_size;
    const float* x     = (const float*)d_in[0];
    const float* W_in  = (const float*)d_in[1];
    const float* b_in  = (const float*)d_in[2];
    const float* W     = (const float*)d_in[3];
    const float* R     = (const float*)d_in[4];
    const float* b     = (const float*)d_in[5];
    const float* W_out = (const float*)d_in[6];
    const float* b_out = (const float*)d_in[7];
    float* out = (float*)d_out;

    cudaFuncSetAttribute(recur_kernel, cudaFuncAttributeMaxDynamicSharedMemorySize, SMEM_BYTES);

    prep_kernel<<<(CL*128*296 + 255)/256, 256>>>(W, R, b, b_in, W_in);  // launch 0
    dummy_kernel<<<1, 32>>>();                                           // launch 1
    dummy_kernel<<<1, 32>>>();                                           // launch 2
    recur_kernel<<<GRID_R, NTHR, SMEM_BYTES>>>(x);                       // launch 3 (ncu)
    epi_kernel<<<BB, 64>>>(W_out, b_out, out);                           // launch 4
}

// round 10
// speedup vs baseline: 1.5340x; 1.5340x over previous
#include <cuda_runtime.h>
#include <cuda_bf16.h>
#include <math.h>

// Problem constants
#define BB    512
#define SS    256
#define IDIM  32
#define HH    256
#define OO    24

// Geometry
#define CL     8                  // CTAs per cluster
#define ROWS   32                 // batch rows per cluster
#define NCLU   (BB/ROWS)          // 16 clusters
#define GRID_R (NCLU*CL)          // 128 CTAs
#define NTHR   256                // 8 warps: 0-3 GEMM+pointwise+broadcast, 4-7 x-stage
#define NCH    18                 // 18 k16 chunks (k 0..287)

#define ASTRIDE 592               // bytes per k-row (576 + 16 pad: conflict-free ldmatrix)
#define A_BYTES (128*ASTRIDE)     // 75776 per precision
#define B_BYTES (32*ASTRIDE)      // 18944 per precision
#define BPAR    (2*B_BYTES)       // 37888: one parity block = [hi | lo]

// SMEM offsets (bytes)
#define A_HI   0
#define A_LO   75776
#define BOFF   151552             // B[p] hi at BOFF + p*BPAR, lo at +B_BYTES
#define SMEM_BYTES (BOFF + 2*BPAR)   // 227328

// Device scratch
__device__ __align__(16) unsigned char g_Ahi[CL*A_BYTES];
__device__ __align__(16) unsigned char g_Alo[CL*A_BYTES];
__device__ float g_bc[CL*128];    // composed bias [rank][m = c*4+q]
__device__ float g_hfinal[BB*HH];

typedef unsigned long long u64;

// ---------------- helpers ----------------
__device__ __forceinline__ unsigned s2u(const void *p) {
    unsigned r;
    asm("{.reg .u64 t; cvta.to.shared.u64 t,%1; cvt.u32.u64 %0,t;}" : "=r"(r) : "l"(p));
    return r;
}
__device__ __forceinline__ unsigned mapa_sh(unsigned a, unsigned r) {
    unsigned o; asm("mapa.shared::cluster.u32 %0,%1,%2;" : "=r"(o) : "r"(a), "r"(r)); return o;
}
__device__ __forceinline__ void stc64(unsigned a, u64 v) {
    asm volatile("st.shared::cluster.b64 [%0],%1;" :: "r"(a), "l"(v) : "memory");
}
__device__ __forceinline__ void carr() { asm volatile("barrier.cluster.arrive.aligned;" ::: "memory"); }
__device__ __forceinline__ void cwait(){ asm volatile("barrier.cluster.wait.aligned;"   ::: "memory"); }
__device__ __forceinline__ void csync(){ carr(); cwait(); }

__device__ __forceinline__ void ldm4(unsigned* r, unsigned a) {
    asm volatile("ldmatrix.sync.aligned.m8n8.x4.shared.b16 {%0,%1,%2,%3},[%4];"
        : "=r"(r[0]), "=r"(r[1]), "=r"(r[2]), "=r"(r[3]) : "r"(a));
}
__device__ __forceinline__ void mma16816(float* d, const unsigned* a, unsigned b0, unsigned b1) {
    asm volatile("mma.sync.aligned.m16n8k16.row.col.f32.bf16.bf16.f32 "
        "{%0,%1,%2,%3},{%4,%5,%6,%7},{%8,%9},{%0,%1,%2,%3};"
        : "+f"(d[0]), "+f"(d[1]), "+f"(d[2]), "+f"(d[3])
        : "r"(a[0]), "r"(a[1]), "r"(a[2]), "r"(a[3]), "r"(b0), "r"(b1));
}

__device__ __forceinline__ float fast_tanh(float x) {
    return 1.f - __fdividef(2.f, __expf(2.f*x) + 1.f);
}
__device__ __forceinline__ u64 pk2f(float a, float b) {
    u64 r; asm("mov.b64 %0,{%1,%2};" : "=l"(r) : "f"(a), "f"(b)); return r;
}
__device__ __forceinline__ void upk2(float &a, float &b, u64 v) {
    asm("mov.b64 {%0,%1},%2;" : "=f"(a), "=f"(b) : "l"(v));
}
__device__ __forceinline__ void split4(const float* v, u64 &vh, u64 &vl) {
    u64 H = 0, L = 0;
    #pragma unroll
    for (int j = 0; j < 4; ++j) {
        __nv_bfloat16 bh = __float2bfloat16(v[j]);
        float fh = __bfloat162float(bh);
        __nv_bfloat16 bl = __float2bfloat16(v[j] - fh);
        H |= (u64)__bfloat16_as_ushort(bh) << (16*j);
        L |= (u64)__bfloat16_as_ushort(bl) << (16*j);
    }
    vh = H; vl = L;
}

// ---------------------------------------------------------------------------
// prep: bf16 hi/lo weight images [rank][m][k], m = c*4+q <-> gate g = q*256+rank*32+c
// ---------------------------------------------------------------------------
__global__ void prep_kernel(const float* __restrict__ W, const float* __restrict__ R,
                            const float* __restrict__ b, const float* __restrict__ b_in,
                            const float* __restrict__ W_in)
{
    int idx = blockIdx.x * blockDim.x + threadIdx.x;
    if (idx < CL*128*296) {
        int kk   = idx % 296;
        int m    = (idx / 296) % 128;
        int rank = idx / (296*128);
        int c = m >> 2, q = m & 3;
        int g = q*256 + rank*32 + c;
        float w = 0.f;
        if (kk < 256) {
            w = W[(size_t)g*512 + 256 + kk] + R[(size_t)g*256 + kk];
        } else if (kk < 288) {
            int i = kk - 256;
            float s = 0.f;
            for (int h = 0; h < HH; ++h) s += W[(size_t)g*512 + h] * W_in[(size_t)h*IDIM + i];
            w = s;
        }
        __nv_bfloat16 hi = __float2bfloat16(w);
        __nv_bfloat16 lo = __float2bfloat16(w - __bfloat162float(hi));
        size_t off = (size_t)rank*A_BYTES + (size_t)m*ASTRIDE + kk*2;
        *(__nv_bfloat16*)(g_Ahi + off) = hi;
        *(__nv_bfloat16*)(g_Alo + off) = lo;
    }
    if (idx < CL*128) {
        int m = idx & 127, rank = idx >> 7;
        int c = m >> 2, q = m & 3;
        int g = q*256 + rank*32 + c;
        float s = b[g];
        for (int h = 0; h < HH; ++h) s += W[(size_t)g*512 + h] * b_in[h];
        g_bc[idx] = s;
    }
}

__global__ void dummy_kernel() {}

// ---------------------------------------------------------------------------
// Recurrence: HMMA 3-term hi/lo; B double-buffered; ONE cluster sync per step.
// warps 0-3: GEMM -> in-register transpose -> pointwise -> DSMEM broadcast.
// warps 4-7: stage x(t+1) into B[p^1].
// ---------------------------------------------------------------------------
__global__ void __cluster_dims__(CL, 1, 1) __launch_bounds__(NTHR, 1)
recur_kernel(const float* __restrict__ x)
{
    extern __shared__ unsigned char smem[];
    const unsigned base = s2u(smem);

    unsigned rank; asm("mov.u32 %0, %%cluster_ctarank;" : "=r"(rank));
    const int cid  = blockIdx.x >> 3;
    const int b0   = cid * ROWS;
    const int tid  = threadIdx.x;
    const int lane = tid & 31;
    const int warp = tid >> 5;

    // ---- load resident A tiles; zero B parity-0 ----
    {
        const float4* sa = (const float4*)(g_Ahi + (size_t)rank*A_BYTES);
        const float4* sb = (const float4*)(g_Alo + (size_t)rank*A_BYTES);
        float4* da = (float4*)(smem + A_HI);
        float4* db = (float4*)(smem + A_LO);
        for (int i = tid; i < A_BYTES/16; i += NTHR) { da[i] = sa[i]; db[i] = sb[i]; }
        float4 z = make_float4(0.f,0.f,0.f,0.f);
        float4* bz = (float4*)(smem + BOFF);
        for (int i = tid; i < BPAR/16; i += NTHR) bz[i] = z;
    }
    __syncthreads();

    // ---- x stager plumbing (warps 4-7): (n_s, 8 features at q_s*8) ----
    const int sidx = tid - 128;
    const int n_s  = (sidx >> 2) & 31;
    const int q_s  = sidx & 3;
    const float* xrb = x + (size_t)(b0 + n_s)*SS*IDIM + q_s*8;
    const unsigned xob = (unsigned)n_s*ASTRIDE + 512 + q_s*16;   // within parity block

    if (warp >= 4) {   // stage x(0) into parity 0
        float4 a0 = *(const float4*)(xrb);
        float4 a1 = *(const float4*)(xrb + 4);
        u64 h0,l0,h1,l1; split4(&a0.x, h0, l0); split4(&a1.x, h1, l1);
        unsigned char* dst = smem + BOFF + xob;
        ((ulonglong2*)dst)[0]             = make_ulonglong2(h0, h1);
        ((ulonglong2*)(dst + B_BYTES))[0] = make_ulonglong2(l0, l1);
    }
    __syncthreads();
    csync();                       // B(0) ready cluster-wide

    // ---- GEMM warp plumbing (warps 0-3) ----
    const unsigned aH  = base + A_HI + (unsigned)(warp*32 + (lane & 15))*ASTRIDE + (lane >> 4)*16;
    const unsigned aL  = aH + (A_LO - A_HI);
    const unsigned bB  = base + BOFF + (unsigned)lane*ASTRIDE;   // + p*BPAR; lo +B_BYTES
    const int r   = lane >> 2;     // 0..7
    const int qt  = lane & 3;
    const int s2  = r & 3;         // gate owner pre-transpose / nj owner post
    const int rb  = r >> 2;        // 0/1 : c parity

    float bias[4][4];              // [gate][k]; c_local = 2k+rb
    float cst[8], nst[8], mst[8];  // u = k*2+np
    unsigned raH[2][8];            // [np][target]: remote B0_HI addr of my h quad
    float* ghf[2];
    if (warp < 4) {
        #pragma unroll
        for (int k = 0; k < 4; ++k)
            #pragma unroll
            for (int j = 0; j < 4; ++j)
                bias[j][k] = g_bc[rank*128 + (warp*8 + 2*k + rb)*4 + j];
        #pragma unroll
        for (int u = 0; u < 8; ++u) { cst[u]=0.f; nst[u]=0.f; mst[u]=0.f; }
        #pragma unroll
        for (int np = 0; np < 2; ++np) {
            int n = s2*8 + qt*2 + np;
            unsigned off = base + BOFF + (unsigned)n*ASTRIDE + (rank*32 + warp*8 + rb*4)*2;
            #pragma unroll
            for (unsigned rr = 0; rr < CL; ++rr) raH[np][rr] = mapa_sh(off, rr);
            ghf[np] = g_hfinal + (size_t)(b0 + n)*HH + rank*32 + warp*8 + rb*4;
        }
    }

    for (int t = 0; t < SS; ++t) {
        const unsigned p  = (unsigned)(t & 1);
        const unsigned p1 = p ^ 1u;

        if (warp >= 4) {
            // ---- stage x(t+1) into B[p1] ----
            if (t + 1 < SS) {
                float4 a0 = *(const float4*)(xrb + (size_t)(t+1)*IDIM);
                float4 a1 = *(const float4*)(xrb + (size_t)(t+1)*IDIM + 4);
                u64 h0,l0,h1,l1; split4(&a0.x, h0, l0); split4(&a1.x, h1, l1);
                unsigned char* dst = smem + BOFF + p1*BPAR + xob;
                ((ulonglong2*)dst)[0]             = make_ulonglong2(h0, h1);
                ((ulonglong2*)(dst + B_BYTES))[0] = make_ulonglong2(l0, l1);
            }
        } else {
            // ---- GEMM: 32m x 32n x 288k, 3-term hi/lo (verbatim from R8) ----
            float d[2][4][4];
            #pragma unroll
            for (int mi = 0; mi < 2; ++mi)
                #pragma unroll
                for (int nj = 0; nj < 4; ++nj)
                    #pragma unroll
                    for (int e = 0; e < 4; ++e) d[mi][nj][e] = 0.f;

            const unsigned bH = bB + p*BPAR;
            #pragma unroll 6
            for (int ch = 0; ch < NCH; ++ch) {
                unsigned ka = ch*32;
                unsigned AH0[4], AH1[4], AL0[4], AL1[4], BHp[4], BHq[4], BLp[4], BLq[4];
                ldm4(AH0, aH + ka); ldm4(AH1, aH + 16*ASTRIDE + ka);
                ldm4(AL0, aL + ka); ldm4(AL1, aL + 16*ASTRIDE + ka);
                ldm4(BHp, bH + ka); ldm4(BHq, bH + ka + 16);
                ldm4(BLp, bH + B_BYTES + ka); ldm4(BLq, bH + B_BYTES + ka + 16);
                #pragma unroll
                for (int nj = 0; nj < 4; ++nj) {
                    mma16816(d[0][nj], AH0, BHp[nj], BHq[nj]);
                    mma16816(d[0][nj], AL0, BHp[nj], BHq[nj]);
                    mma16816(d[0][nj], AH0, BLp[nj], BLq[nj]);
                    mma16816(d[1][nj], AH1, BHp[nj], BHq[nj]);
                    mma16816(d[1][nj], AL1, BHp[nj], BHq[nj]);
                    mma16816(d[1][nj], AH1, BLp[nj], BLq[nj]);
                }
            }

            // ---- in-register 4x4 gate transpose over lane bits 2-3 ----
            // v[nj][u] (u = k*2+np, k = 2*mi + (e>>1), np = e&1): gate s2 values
            float v[4][8];
            #pragma unroll
            for (int mi = 0; mi < 2; ++mi)
                #pragma unroll
                for (int nj = 0; nj < 4; ++nj)
                    #pragma unroll
                    for (int e = 0; e < 4; ++e)
                        v[nj][(2*mi + (e>>1))*2 + (e&1)] = d[mi][nj][e];

            float t1[4][8], g[4][8];
            #pragma unroll
            for (int j = 0; j < 4; ++j) {
                bool sw = ((s2 ^ j) & 1) != 0;
                #pragma unroll
                for (int u = 0; u < 8; ++u) {
                    float ov = __shfl_xor_sync(0xffffffffu, v[j^1][u], 4);
                    t1[j][u] = sw ? ov : v[j][u];
                }
            }
            #pragma unroll
            for (int j = 0; j < 4; ++j) {
                bool sw = ((s2 ^ j) & 2) != 0;
                #pragma unroll
                for (int u = 0; u < 8; ++u) {
                    float ov = __shfl_xor_sync(0xffffffffu, t1[j^2][u], 8);
                    g[j][u] = sw ? ov : t1[j][u];
                }
            }
            // g[j][u]: gate j, cell (c_local = 2k+rb, n = s2*8+qt*2+np)

            // ---- pointwise sLSTM (8 cells) ----
            float hq[4][2];
            #pragma unroll
            for (int k = 0; k < 4; ++k)
                #pragma unroll
                for (int np = 0; np < 2; ++np) {
                    int u = k*2 + np;
                    float gi = g[0][u] + bias[0][k];
                    float gf = g[1][u] + bias[1][k];
                    float gz = g[2][u] + bias[2][k];
                    float go = g[3][u] + bias[3][k];
                    float lf  = -__logf(1.f + __expf(-gf));
                    float mn  = fmaxf(lf + mst[u], gi);
                    float ipr = __expf(gi - mn);
                    float fp  = __expf(lf + mst[u] - mn);
                    float cn  = fp*cst[u] + ipr*fast_tanh(gz);
                    float nn  = fp*nst[u] + ipr;
                    float so  = __fdividef(1.f, 1.f + __expf(-go));
                    hq[k][np] = so * fast_tanh(__fdividef(cn, nn));
                    cst[u]=cn; nst[u]=nn; mst[u]=mn;
                }

            // ---- c-contiguity exchange (bfly 16) + output ----
            #pragma unroll
            for (int np = 0; np < 2; ++np) {
                u64 snd = rb ? pk2f(hq[0][np], hq[1][np]) : pk2f(hq[2][np], hq[3][np]);
                u64 got = __shfl_xor_sync(0xffffffffu, snd, 16);
                float gx, gy; upk2(gx, gy, got);
                float qd[4];
                if (rb == 0) { qd[0]=hq[0][np]; qd[1]=gx; qd[2]=hq[1][np]; qd[3]=gy; }
                else         { qd[0]=gx; qd[1]=hq[2][np]; qd[2]=gy; qd[3]=hq[3][np]; }
                if (t + 1 < SS) {
                    u64 vH, vL; split4(qd, vH, vL);
                    unsigned add = p1*BPAR;
                    #pragma unroll
                    for (unsigned rr = 0; rr < CL; ++rr) {
                        stc64(raH[np][rr] + add, vH);
                        stc64(raH[np][rr] + add + B_BYTES, vL);
                    }
                } else {
                    *(float4*)ghf[np] = make_float4(qd[0], qd[1], qd[2], qd[3]);
                }
            }
        }

        if (t + 1 < SS) csync();   // release writes to B[p1]; acquire everyone's
    }
}

// ---------------------------------------------------------------------------
// Epilogue: out = h @ W_out^T + b_out, then layernorm over O=24
// ---------------------------------------------------------------------------
__global__ void __launch_bounds__(64) epi_kernel(const float* __restrict__ Wo,
                                                 const float* __restrict__ bo,
                                                 float* __restrict__ out)
{
    __shared__ float hrow[HH];
    __shared__ float ov[OO];
    __shared__ float s_mu, s_rs;
    int b = blockIdx.x, tid = threadIdx.x;

    const float4* hs = (const float4*)(g_hfinal + (size_t)b*HH);
    for (int i = tid; i < HH/4; i += 64) ((float4*)hrow)[i] = hs[i];
    __syncthreads();

    if (tid < OO) {
        float s = bo[tid];
        const float* w = Wo + (size_t)tid*HH;
        #pragma unroll 8
        for (int k = 0; k < HH; ++k) s += hrow[k]*w[k];
        ov[tid] = s;
    }
    __syncthreads();
    if (tid == 0) {
        float mu = 0.f;
        for (int o = 0; o < OO; ++o) mu += ov[o];
        mu *= (1.f/OO);
        float va = 0.f;
        for (int o = 0; o < OO; ++o) { float d = ov[o]-mu; va += d*d; }
        va *= (1.f/OO);
        s_mu = mu; s_rs = rsqrtf(va + 1e-5f);
    }
    __syncthreads();
    if (tid < OO) out[(size_t)b*OO + tid] = (ov[tid]-s_mu)*s_rs;
}

// ---------------------------------------------------------------------------
extern "C" void kernel_launch(void* const* d_in, const int* in_sizes, int n_in,
                              void* d_out, int out_size)
{
    (void)in_sizes; (void)n_in; (void)out_size;
    const float* x     = (const float*)d_in[0];
    const float* W_in  = (const float*)d_in[1];
    const float* b_in  = (const float*)d_in[2];
    const float* W     = (const float*)d_in[3];
    const float* R     = (const float*)d_in[4];
    const float* b     = (const float*)d_in[5];
    const float* W_out = (const float*)d_in[6];
    const float* b_out = (const float*)d_in[7];
    float* out = (float*)d_out;

    cudaFuncSetAttribute(recur_kernel, cudaFuncAttributeMaxDynamicSharedMemorySize, SMEM_BYTES);

    prep_kernel<<<(CL*128*296 + 255)/256, 256>>>(W, R, b, b_in, W_in);  // launch 0
    dummy_kernel<<<1, 32>>>();                                           // launch 1
    dummy_kernel<<<1, 32>>>();                                           // launch 2
    recur_kernel<<<GRID_R, NTHR, SMEM_BYTES>>>(x);                       // launch 3 (ncu)
    epi_kernel<<<BB, 64>>>(W_out, b_out, out);                           // launch 4
}